// round 4
// baseline (speedup 1.0000x reference)
#include <cuda_runtime.h>

#define BB 2
#define CC 256
#define NPIX 65536
#define NL 8
#define NCHUNK 256
#define NBL (BB*NL)

// ---------------- scratch (static device globals; no runtime allocation) ----------------
__device__ int g_is64_c, g_is64_s;
__device__ int g_hist_c[NCHUNK][NL];
__device__ int g_hist_s[NCHUNK][NL];
__device__ int g_base_c[NCHUNK][NL];
__device__ int g_base_s[NCHUNK][NL];
__device__ int g_off_c[NL+1];
__device__ int g_off_s[NL+1];
__device__ int g_cnt_c[NL];
__device__ int g_cnt_s[NL];
__device__ int g_guide[NL];
__device__ unsigned char g_lbl_c[NPIX];
__device__ unsigned char g_lbl_s[NPIX];
__device__ int g_idx_c[NPIX];
__device__ int g_idx_s[NPIX];
__device__ float g_mean_c[BB][NL][CC];
__device__ float g_mean_s[BB][NL][CC];
__device__ float g_cg[33554432];          // [B][C][N] content features, label-compacted (128 MB)
__device__ float g_sg[33554432];          // style, label-compacted (128 MB)
__device__ float g_covc[NBL][CC][CC];     // cov_c -> in-place Cholesky L_c
__device__ float g_covs[NBL][CC][CC];     // cov_s -> in-place Cholesky L_s
__device__ float g_linv[NBL][CC][CC];     // inv(L_c)
__device__ float g_T[NBL][CC][CC];        // T = L_s * inv(L_c)  (lower triangular)

__constant__ int c_TI[10] = {0,1,1,2,2,2,3,3,3,3};
__constant__ int c_TJ[10] = {0,0,1,0,1,2,0,1,2,3};

// ---------------- 0. mask dtype detection (int64 vs int32) ----------------
// If the buffer holds int64 labels (<8), every odd 32-bit word is a zero high-half.
// If int32, odd words are random labels in [0,8): OR over 4096 of them is ~never 0.
__global__ void k_detect(const unsigned int* __restrict__ cm, const unsigned int* __restrict__ sm) {
    __shared__ unsigned int oc[256], os[256];
    int t = threadIdx.x;
    unsigned int a = 0, b = 0;
    for (int i = t; i < 4096; i += 256) { a |= cm[2*i + 1]; b |= sm[2*i + 1]; }
    oc[t] = a; os[t] = b;
    __syncthreads();
    for (int s = 128; s > 0; s >>= 1) {
        if (t < s) { oc[t] |= oc[t + s]; os[t] |= os[t + s]; }
        __syncthreads();
    }
    if (t == 0) { g_is64_c = (oc[0] == 0); g_is64_s = (os[0] == 0); }
}

// ---------------- 1. per-chunk histograms + int8 label cache ----------------
__global__ void k_hist(const unsigned int* __restrict__ cm, const unsigned int* __restrict__ sm) {
    __shared__ int hc[NL], hs[NL];
    int t = threadIdx.x;
    if (t < NL) { hc[t] = 0; hs[t] = 0; }
    __syncthreads();
    int p = (blockIdx.x << 8) + t;
    int lc = (int)(g_is64_c ? cm[2*p] : cm[p]) & 7;
    int ls = (int)(g_is64_s ? sm[2*p] : sm[p]) & 7;
    g_lbl_c[p] = (unsigned char)lc;
    g_lbl_s[p] = (unsigned char)ls;
    atomicAdd(&hc[lc], 1);
    atomicAdd(&hs[ls], 1);
    __syncthreads();
    if (t < NL) { g_hist_c[blockIdx.x][t] = hc[t]; g_hist_s[blockIdx.x][t] = hs[t]; }
}

// ---------------- 2. totals, offsets, per-chunk bases, guide flags ----------------
__global__ void k_off() {
    int t = threadIdx.x;
    if (t < NL) {
        int run = 0;
        for (int ch = 0; ch < NCHUNK; ch++) { g_base_c[ch][t] = run; run += g_hist_c[ch][t]; }
        g_cnt_c[t] = run;
    } else if (t < 2*NL) {
        int l = t - NL; int run = 0;
        for (int ch = 0; ch < NCHUNK; ch++) { g_base_s[ch][l] = run; run += g_hist_s[ch][l]; }
        g_cnt_s[l] = run;
    }
    __syncthreads();
    if (t == 0) {
        int oc = 0, os = 0;
        for (int l = 0; l < NL; l++) {
            g_off_c[l] = oc; oc += g_cnt_c[l];
            g_off_s[l] = os; os += g_cnt_s[l];
        }
        g_off_c[NL] = oc; g_off_s[NL] = os;
        for (int l = 0; l < NL; l++) {
            long long a = g_cnt_c[l], b = g_cnt_s[l];
            g_guide[l] = (a > 10 && b > 10 && a < 10*b && b < 10*a) ? 1 : 0;
        }
    }
}

// ---------------- 3. stable counting-sort scatter (deterministic) ----------------
__global__ void k_scatter() {
    __shared__ unsigned char lc[256], ls[256];
    int t = threadIdx.x, ch = blockIdx.x;
    lc[t] = g_lbl_c[(ch << 8) + t];
    ls[t] = g_lbl_s[(ch << 8) + t];
    __syncthreads();
    if (t == 0) {
        int cur[NL];
        for (int l = 0; l < NL; l++) cur[l] = g_off_c[l] + g_base_c[ch][l];
        for (int i = 0; i < 256; i++) { int l = lc[i]; g_idx_c[cur[l]++] = (ch << 8) + i; }
    } else if (t == 32) {
        int cur[NL];
        for (int l = 0; l < NL; l++) cur[l] = g_off_s[l] + g_base_s[ch][l];
        for (int i = 0; i < 256; i++) { int l = ls[i]; g_idx_s[cur[l]++] = (ch << 8) + i; }
    }
}

// ---------------- 4. out = c_feat ----------------
__global__ void k_copy(const float* __restrict__ cf, float* __restrict__ out) {
    long i = ((long)blockIdx.x << 8) + threadIdx.x;
    ((float4*)out)[i] = ((const float4*)cf)[i];
}

// ---------------- 5. compact features by label order ----------------
__global__ void k_gather(const float* __restrict__ cf, const float* __restrict__ sf) {
    int which = blockIdx.y;
    long i = ((long)blockIdx.x << 8) + threadIdx.x;
    const int*   idx = which ? g_idx_s : g_idx_c;
    const float* f   = which ? sf      : cf;
    float*       dst = which ? g_sg    : g_cg;
    int  j   = (int)(i & (NPIX - 1));
    long row = i >> 16;
    dst[i] = f[(row << 16) + idx[j]];
}

// ---------------- 6. per-(b,label,channel) masked means ----------------
__global__ __launch_bounds__(256) void k_mean(const float* __restrict__ cf, const float* __restrict__ sf) {
    int c = blockIdx.x, b = blockIdx.y, w = blockIdx.z;
    const float* f = (w ? sf : cf) + ((long)(b*CC + c)) * NPIX;
    const unsigned char* lbl = w ? g_lbl_s : g_lbl_c;
    float acc[8];
    #pragma unroll
    for (int q = 0; q < 8; q++) acc[q] = 0.f;
    for (int p = threadIdx.x; p < NPIX; p += 256) {
        float v = f[p];
        int l = lbl[p];
        #pragma unroll
        for (int q = 0; q < 8; q++) acc[q] += (l == q) ? v : 0.f;
    }
    __shared__ float red[256];
    const int* cnt = w ? g_cnt_s : g_cnt_c;
    for (int q = 0; q < 8; q++) {
        red[threadIdx.x] = acc[q];
        __syncthreads();
        for (int s = 128; s > 0; s >>= 1) {
            if (threadIdx.x < s) red[threadIdx.x] += red[threadIdx.x + s];
            __syncthreads();
        }
        if (threadIdx.x == 0) {
            int n = cnt[q];
            float m = (n > 0) ? red[0] / (float)n : 0.f;
            if (w) g_mean_s[b][q][c] = m; else g_mean_c[b][q][c] = m;
        }
        __syncthreads();
    }
}

// ---------------- 7. covariance SYRK (lower-triangle tiles + mirror) ----------------
__global__ __launch_bounds__(256) void k_cov() {
    int pair = blockIdx.x;
    int bl   = blockIdx.y;
    int w    = blockIdx.z;
    int l = bl & 7, b = bl >> 3;
    if (!g_guide[l]) return;
    int cnt = w ? g_cnt_s[l] : g_cnt_c[l];
    int off = w ? g_off_s[l] : g_off_c[l];
    const float* src  = (w ? g_sg : g_cg) + ((long)b*CC) * NPIX;
    const float* mean = w ? g_mean_s[b][l] : g_mean_c[b][l];
    float (*cov)[CC]  = w ? g_covs[bl] : g_covc[bl];
    int ti = c_TI[pair], tj = c_TJ[pair];

    __shared__ __align__(16) float As[16][68];
    __shared__ __align__(16) float Bs[16][68];
    int t  = threadIdx.x;
    int tx = t & 15, ty = t >> 4;
    int lk = t & 15, lm = (t >> 4) << 2;
    float ma[4], mb[4];
    #pragma unroll
    for (int i = 0; i < 4; i++) { ma[i] = mean[ti*64 + lm + i]; mb[i] = mean[tj*64 + lm + i]; }
    float acc[4][4];
    #pragma unroll
    for (int i = 0; i < 4; i++)
        #pragma unroll
        for (int j = 0; j < 4; j++) acc[i][j] = 0.f;

    for (int kk = 0; kk < cnt; kk += 16) {
        int col = off + kk + lk;
        bool ok = (kk + lk) < cnt;
        #pragma unroll
        for (int i = 0; i < 4; i++) {
            As[lk][lm + i] = ok ? (src[(long)(ti*64 + lm + i)*NPIX + col] - ma[i]) : 0.f;
            Bs[lk][lm + i] = ok ? (src[(long)(tj*64 + lm + i)*NPIX + col] - mb[i]) : 0.f;
        }
        __syncthreads();
        #pragma unroll
        for (int k = 0; k < 16; k++) {
            float4 a4 = *(const float4*)&As[k][ty << 2];
            float4 b4 = *(const float4*)&Bs[k][tx << 2];
            float a[4]  = {a4.x, a4.y, a4.z, a4.w};
            float bv[4] = {b4.x, b4.y, b4.z, b4.w};
            #pragma unroll
            for (int i = 0; i < 4; i++)
                #pragma unroll
                for (int j = 0; j < 4; j++) acc[i][j] += a[i] * bv[j];
        }
        __syncthreads();
    }
    float inv = 1.f / (float)(cnt - 1);
    #pragma unroll
    for (int i = 0; i < 4; i++) {
        int r = ti*64 + (ty << 2) + i;
        #pragma unroll
        for (int j = 0; j < 4; j++) {
            int c2 = tj*64 + (tx << 2) + j;
            float v = acc[i][j] * inv;
            cov[r][c2] = v;
            if (ti != tj) cov[c2][r] = v;
        }
    }
}

// ---------------- 8. in-place right-looking Cholesky (32 matrices) ----------------
__global__ __launch_bounds__(256) void k_chol() {
    int w = blockIdx.x >> 4, bl = blockIdx.x & 15;
    if (!g_guide[bl & 7]) return;
    float* M = w ? &g_covs[bl][0][0] : &g_covc[bl][0][0];
    int t = threadIdx.x, lane = t & 31, warp = t >> 5;
    __shared__ __align__(16) float colk[256];
    __shared__ float diag;
    for (int k = 0; k < CC; k++) {
        if (t == 0) { float d = sqrtf(M[k*CC + k]); M[k*CC + k] = d; diag = d; }
        __syncthreads();
        float d = diag;
        float cv = 0.f;
        if (t > k) { cv = M[t*CC + k] / d; M[t*CC + k] = cv; }
        colk[t] = cv;                 // zero for t <= k: protects finalized columns below
        __syncthreads();
        int q0 = (k + 1) >> 2;
        for (int i = k + 1 + warp; i < CC; i += 8) {
            float lik = colk[i];
            int qend = i >> 2;        // columns beyond i touch upper junk only (never read)
            for (int q = q0 + lane; q <= qend; q += 32) {
                float4 mv = *(float4*)&M[i*CC + (q << 2)];
                float4 cq = *(const float4*)&colk[q << 2];
                mv.x -= lik * cq.x; mv.y -= lik * cq.y;
                mv.z -= lik * cq.z; mv.w -= lik * cq.w;
                *(float4*)&M[i*CC + (q << 2)] = mv;
            }
        }
        __syncthreads();
    }
}

// ---------------- 9. triangular inverse of L_c (column per thread) ----------------
__global__ __launch_bounds__(256) void k_inv() {
    int bl = blockIdx.x;
    if (!g_guide[bl & 7]) return;
    const float* L = &g_covc[bl][0][0];
    float*       X = &g_linv[bl][0][0];
    int j = threadIdx.x;
    float x[CC];                      // local memory, L1-resident
    for (int i = 0; i < CC; i++) {
        float v;
        if (i < j)      v = 0.f;
        else if (i == j) v = 1.f / L[i*CC + i];
        else {
            float s0 = 0.f, s1 = 0.f, s2 = 0.f, s3 = 0.f;
            const float* Lr = &L[i*CC];
            int k = j;
            for (; k + 4 <= i; k += 4) {
                s0 += Lr[k]   * x[k];
                s1 += Lr[k+1] * x[k+1];
                s2 += Lr[k+2] * x[k+2];
                s3 += Lr[k+3] * x[k+3];
            }
            for (; k < i; k++) s0 += Lr[k] * x[k];
            v = -((s0 + s1) + (s2 + s3)) / L[i*CC + i];
        }
        x[i] = v;
        X[i*CC + j] = v;
    }
}

// ---------------- 10. T = L_s * inv(L_c)  (lower triangular) ----------------
__global__ __launch_bounds__(256) void k_T() {
    int bl = blockIdx.y, c = blockIdx.x;
    if (!g_guide[bl & 7]) return;
    const float* Ls = &g_covs[bl][0][0];
    const float* Li = &g_linv[bl][0][0];
    float*       T  = &g_T[bl][0][0];
    int e = threadIdx.x;
    __shared__ float lsrow[CC];
    lsrow[e] = Ls[c*CC + e];
    __syncthreads();
    float s = 0.f;
    for (int d = e; d <= c; d++) s += lsrow[d] * Li[d*CC + e];
    T[c*CC + e] = s;                  // zero when e > c (empty loop)
}

// ---------------- 11. colored = T*(x - mu_c) + mu_s, scatter into out ----------------
__global__ __launch_bounds__(256) void k_color(float* __restrict__ out) {
    int bl = blockIdx.z; int l = bl & 7, b = bl >> 3;
    if (!g_guide[l]) return;
    int cnt = g_cnt_c[l];
    int j0  = blockIdx.x << 6;
    if (j0 >= cnt) return;
    int ri = blockIdx.y;
    int r0 = ri << 7;
    int kend = r0 + 128;              // T lower-triangular: cols >= kend are zero for these rows
    int off = g_off_c[l];
    const float* T     = &g_T[bl][0][0];
    const float* src   = g_cg + ((long)b*CC) * NPIX;
    const float* meanc = g_mean_c[b][l];
    const float* means = g_mean_s[b][l];

    __shared__ __align__(16) float As[16][132];
    __shared__ __align__(16) float Bs[16][68];
    int t  = threadIdx.x;
    int tx = t & 15, ty = t >> 4;
    float acc[8][4];
    #pragma unroll
    for (int i = 0; i < 8; i++)
        #pragma unroll
        for (int j = 0; j < 4; j++) acc[i][j] = 0.f;

    int am  = t >> 1;                 // 0..127
    int ak0 = (t & 1) << 3;           // 0 or 8
    int bk  = t >> 4;                 // 0..15
    int bj  = (t & 15) << 2;

    for (int kk = 0; kk < kend; kk += 16) {
        #pragma unroll
        for (int i = 0; i < 8; i++)
            As[ak0 + i][am] = T[(long)(r0 + am)*CC + kk + ak0 + i];
        float mk = meanc[kk + bk];
        #pragma unroll
        for (int i = 0; i < 4; i++) {
            int jj = j0 + bj + i;
            Bs[bk][bj + i] = (jj < cnt) ? (src[(long)(kk + bk)*NPIX + off + jj] - mk) : 0.f;
        }
        __syncthreads();
        #pragma unroll
        for (int k = 0; k < 16; k++) {
            float4 a0 = *(const float4*)&As[k][ty << 3];
            float4 a1 = *(const float4*)&As[k][(ty << 3) + 4];
            float4 b4 = *(const float4*)&Bs[k][tx << 2];
            float a[8]  = {a0.x, a0.y, a0.z, a0.w, a1.x, a1.y, a1.z, a1.w};
            float bv[4] = {b4.x, b4.y, b4.z, b4.w};
            #pragma unroll
            for (int i = 0; i < 8; i++)
                #pragma unroll
                for (int j = 0; j < 4; j++) acc[i][j] += a[i] * bv[j];
        }
        __syncthreads();
    }
    int jbase = j0 + (tx << 2);
    int pix[4];
    #pragma unroll
    for (int j = 0; j < 4; j++)
        pix[j] = (jbase + j < cnt) ? g_idx_c[off + jbase + j] : -1;
    #pragma unroll
    for (int i = 0; i < 8; i++) {
        int c = r0 + (ty << 3) + i;
        float sm = means[c];
        long rowbase = ((long)(b*CC + c)) << 16;
        #pragma unroll
        for (int j = 0; j < 4; j++)
            if (pix[j] >= 0) out[rowbase + pix[j]] = acc[i][j] + sm;
    }
}

// ---------------- launcher ----------------
extern "C" void kernel_launch(void* const* d_in, const int* in_sizes, int n_in,
                              void* d_out, int out_size) {
    const float*        cf = (const float*)d_in[0];
    const float*        sf = (const float*)d_in[1];
    const unsigned int* cm = (const unsigned int*)d_in[2];
    const unsigned int* sm = (const unsigned int*)d_in[3];
    float* out = (float*)d_out;

    k_detect <<<1, 256>>>(cm, sm);
    k_hist   <<<NCHUNK, 256>>>(cm, sm);
    k_off    <<<1, 64>>>();
    k_scatter<<<NCHUNK, 256>>>();
    k_copy   <<<32768, 256>>>(cf, out);
    k_gather <<<dim3(131072, 2), 256>>>(cf, sf);
    k_mean   <<<dim3(CC, BB, 2), 256>>>(cf, sf);
    k_cov    <<<dim3(10, NBL, 2), 256>>>();
    k_chol   <<<32, 256>>>();
    k_inv    <<<16, 256>>>();
    k_T      <<<dim3(CC, NBL), 256>>>();
    k_color  <<<dim3(1024, 2, NBL), 256>>>(out);
}

// round 6
// speedup vs baseline: 1.1037x; 1.1037x over previous
#include <cuda_runtime.h>

#define BB 2
#define CC 256
#define NPIX 65536
#define NL 8
#define NCHUNK 256
#define NBL (BB*NL)

// ---------------- scratch (static device globals; no runtime allocation) ----------------
__device__ int g_is64_c, g_is64_s;
__device__ int g_hist_c[NCHUNK][NL];
__device__ int g_hist_s[NCHUNK][NL];
__device__ int g_base_c[NCHUNK][NL];
__device__ int g_base_s[NCHUNK][NL];
__device__ int g_off_c[NL+1];
__device__ int g_off_s[NL+1];
__device__ int g_cnt_c[NL];
__device__ int g_cnt_s[NL];
__device__ int g_guide[NL];
__device__ unsigned char g_lbl_c[NPIX];
__device__ unsigned char g_lbl_s[NPIX];
__device__ int g_idx_c[NPIX];
__device__ int g_idx_s[NPIX];
__device__ float g_mean_c[BB][NL][CC];
__device__ float g_mean_s[BB][NL][CC];
__device__ float g_corr[NBL][CC];         // mu_s - T*mu_c  (per bl, per out channel)
__device__ float g_cg[33554432];          // [B][C][N] content features, label-compacted (128 MB)
__device__ float g_sg[33554432];          // style, label-compacted (128 MB)
__device__ float g_covc[NBL][CC][CC];     // cov_c -> in-place Cholesky L_c
__device__ float g_covs[NBL][CC][CC];     // cov_s -> in-place Cholesky L_s
__device__ float g_linv[NBL][CC][CC];     // inv(L_c)
__device__ float g_T[NBL][CC][CC];        // T = L_s * inv(L_c)  (lower triangular)

__constant__ int c_TI[10] = {0,1,1,2,2,2,3,3,3,3};
__constant__ int c_TJ[10] = {0,0,1,0,1,2,0,1,2,3};

// ---------------- 0. mask dtype detection (int64 vs int32) ----------------
__global__ void k_detect(const unsigned int* __restrict__ cm, const unsigned int* __restrict__ sm) {
    __shared__ unsigned int oc[256], os[256];
    int t = threadIdx.x;
    unsigned int a = 0, b = 0;
    for (int i = t; i < 4096; i += 256) { a |= cm[2*i + 1]; b |= sm[2*i + 1]; }
    oc[t] = a; os[t] = b;
    __syncthreads();
    for (int s = 128; s > 0; s >>= 1) {
        if (t < s) { oc[t] |= oc[t + s]; os[t] |= os[t + s]; }
        __syncthreads();
    }
    if (t == 0) { g_is64_c = (oc[0] == 0); g_is64_s = (os[0] == 0); }
}

// ---------------- 1. per-chunk histograms + int8 label cache ----------------
__global__ void k_hist(const unsigned int* __restrict__ cm, const unsigned int* __restrict__ sm) {
    __shared__ int hc[NL], hs[NL];
    int t = threadIdx.x;
    if (t < NL) { hc[t] = 0; hs[t] = 0; }
    __syncthreads();
    int p = (blockIdx.x << 8) + t;
    int lc = (int)(g_is64_c ? cm[2*p] : cm[p]) & 7;
    int ls = (int)(g_is64_s ? sm[2*p] : sm[p]) & 7;
    g_lbl_c[p] = (unsigned char)lc;
    g_lbl_s[p] = (unsigned char)ls;
    atomicAdd(&hc[lc], 1);
    atomicAdd(&hs[ls], 1);
    __syncthreads();
    if (t < NL) { g_hist_c[blockIdx.x][t] = hc[t]; g_hist_s[blockIdx.x][t] = hs[t]; }
}

// ---------------- 2. totals, offsets, per-chunk bases, guide flags ----------------
__global__ void k_off() {
    int t = threadIdx.x;
    if (t < NL) {
        int run = 0;
        for (int ch = 0; ch < NCHUNK; ch++) { g_base_c[ch][t] = run; run += g_hist_c[ch][t]; }
        g_cnt_c[t] = run;
    } else if (t < 2*NL) {
        int l = t - NL; int run = 0;
        for (int ch = 0; ch < NCHUNK; ch++) { g_base_s[ch][l] = run; run += g_hist_s[ch][l]; }
        g_cnt_s[l] = run;
    }
    __syncthreads();
    if (t == 0) {
        int oc = 0, os = 0;
        for (int l = 0; l < NL; l++) {
            g_off_c[l] = oc; oc += g_cnt_c[l];
            g_off_s[l] = os; os += g_cnt_s[l];
        }
        g_off_c[NL] = oc; g_off_s[NL] = os;
        for (int l = 0; l < NL; l++) {
            long long a = g_cnt_c[l], b = g_cnt_s[l];
            g_guide[l] = (a > 10 && b > 10 && a < 10*b && b < 10*a) ? 1 : 0;
        }
    }
}

// ---------------- 3. stable counting-sort scatter (deterministic) ----------------
__global__ void k_scatter() {
    __shared__ unsigned char lc[256], ls[256];
    int t = threadIdx.x, ch = blockIdx.x;
    lc[t] = g_lbl_c[(ch << 8) + t];
    ls[t] = g_lbl_s[(ch << 8) + t];
    __syncthreads();
    if (t == 0) {
        int cur[NL];
        for (int l = 0; l < NL; l++) cur[l] = g_off_c[l] + g_base_c[ch][l];
        for (int i = 0; i < 256; i++) { int l = lc[i]; g_idx_c[cur[l]++] = (ch << 8) + i; }
    } else if (t == 32) {
        int cur[NL];
        for (int l = 0; l < NL; l++) cur[l] = g_off_s[l] + g_base_s[ch][l];
        for (int i = 0; i < 256; i++) { int l = ls[i]; g_idx_s[cur[l]++] = (ch << 8) + i; }
    }
}

// ---------------- 4. out = c_feat ----------------
__global__ void k_copy(const float* __restrict__ cf, float* __restrict__ out) {
    long i = ((long)blockIdx.x << 8) + threadIdx.x;
    ((float4*)out)[i] = ((const float4*)cf)[i];
}

// ---------------- 5. compact features by label order (vectorized) ----------------
__global__ void k_gather(const float* __restrict__ cf, const float* __restrict__ sf) {
    int which = blockIdx.y;
    long i4 = ((long)blockIdx.x << 8) + threadIdx.x;   // float4 index
    const int*   idx = which ? g_idx_s : g_idx_c;
    const float* f   = which ? sf      : cf;
    float*       dst = which ? g_sg    : g_cg;
    int  j4  = (int)(i4 & ((NPIX >> 2) - 1));
    long row = i4 >> 14;                                // NPIX/4 = 16384
    const int4 id = ((const int4*)idx)[j4];
    const float* fr = f + (row << 16);
    float4 v;
    v.x = fr[id.x]; v.y = fr[id.y]; v.z = fr[id.z]; v.w = fr[id.w];
    ((float4*)dst)[i4] = v;
}

// ---------------- 6. per-(b,label,channel) means from compacted segments ----------------
__global__ __launch_bounds__(256) void k_sum() {
    int c = blockIdx.x, b = blockIdx.y, w = blockIdx.z;
    const float* src = (w ? g_sg : g_cg) + ((long)(b*CC + c)) * NPIX;
    const int* off = w ? g_off_s : g_off_c;
    __shared__ float red[256];
    int t = threadIdx.x;
    for (int l = 0; l < NL; l++) {
        int lo = off[l], hi = off[l+1];
        float s = 0.f;
        for (int p = lo + t; p < hi; p += 256) s += src[p];
        red[t] = s;
        __syncthreads();
        for (int q = 128; q > 0; q >>= 1) {
            if (t < q) red[t] += red[t + q];
            __syncthreads();
        }
        if (t == 0) {
            int n = hi - lo;
            float m = (n > 0) ? red[0] / (float)n : 0.f;
            if (w) g_mean_s[b][l][c] = m; else g_mean_c[b][l][c] = m;
        }
        __syncthreads();
    }
}

// ---------------- 7. raw SYRK + rank-1 mean correction (double-buffered) ----------------
__global__ __launch_bounds__(256) void k_cov() {
    int pair = blockIdx.x;
    int bl   = blockIdx.y;
    int w    = blockIdx.z;
    int l = bl & 7, b = bl >> 3;
    if (!g_guide[l]) return;
    int cnt = w ? g_cnt_s[l] : g_cnt_c[l];
    int off = w ? g_off_s[l] : g_off_c[l];
    const float* src  = (w ? g_sg : g_cg) + ((long)b*CC) * NPIX;
    const float* mean = w ? g_mean_s[b][l] : g_mean_c[b][l];
    float (*cov)[CC]  = w ? g_covs[bl] : g_covc[bl];
    int ti = c_TI[pair], tj = c_TJ[pair];

    __shared__ __align__(16) float As[16][68];
    __shared__ __align__(16) float Bs[16][68];
    int t  = threadIdx.x;
    int tx = t & 15, ty = t >> 4;
    int lk = t & 15, lm = (t >> 4) << 2;
    const float* pa = src + (long)(ti*64 + lm)*NPIX + off;
    const float* pb = src + (long)(tj*64 + lm)*NPIX + off;
    float acc[4][4];
    #pragma unroll
    for (int i = 0; i < 4; i++)
        #pragma unroll
        for (int j = 0; j < 4; j++) acc[i][j] = 0.f;

    int niter = (cnt + 15) >> 4;
    float rA[4], rB[4];
    {   // prologue: tile 0 -> regs
        bool ok = lk < cnt;
        #pragma unroll
        for (int i = 0; i < 4; i++) {
            rA[i] = ok ? pa[(long)i*NPIX + lk] : 0.f;
            rB[i] = ok ? pb[(long)i*NPIX + lk] : 0.f;
        }
    }
    for (int it = 0; it < niter; it++) {
        #pragma unroll
        for (int i = 0; i < 4; i++) { As[lk][lm + i] = rA[i]; Bs[lk][lm + i] = rB[i]; }
        __syncthreads();
        if (it + 1 < niter) {                 // prefetch next tile (latency hidden by compute)
            int nc = ((it + 1) << 4) + lk;
            bool ok = nc < cnt;
            #pragma unroll
            for (int i = 0; i < 4; i++) {
                rA[i] = ok ? pa[(long)i*NPIX + nc] : 0.f;
                rB[i] = ok ? pb[(long)i*NPIX + nc] : 0.f;
            }
        }
        #pragma unroll
        for (int k = 0; k < 16; k++) {
            float4 a4 = *(const float4*)&As[k][ty << 2];
            float4 b4 = *(const float4*)&Bs[k][tx << 2];
            float a[4]  = {a4.x, a4.y, a4.z, a4.w};
            float bv[4] = {b4.x, b4.y, b4.z, b4.w};
            #pragma unroll
            for (int i = 0; i < 4; i++)
                #pragma unroll
                for (int j = 0; j < 4; j++) acc[i][j] += a[i] * bv[j];
        }
        __syncthreads();
    }
    float a   = (float)cnt;
    float inv = 1.f / (a - 1.f);
    float mr[4], mc[4];
    #pragma unroll
    for (int i = 0; i < 4; i++) {
        mr[i] = mean[ti*64 + (ty << 2) + i];
        mc[i] = mean[tj*64 + (tx << 2) + i];
    }
    #pragma unroll
    for (int i = 0; i < 4; i++) {
        int r = ti*64 + (ty << 2) + i;
        #pragma unroll
        for (int j = 0; j < 4; j++) {
            int c2 = tj*64 + (tx << 2) + j;
            float v = (acc[i][j] - a * mr[i] * mc[j]) * inv;
            cov[r][c2] = v;
            if (ti != tj) cov[c2][r] = v;
        }
    }
}

// ---------------- 8. in-place right-looking Cholesky (32 matrices) ----------------
__global__ __launch_bounds__(256) void k_chol() {
    int w = blockIdx.x >> 4, bl = blockIdx.x & 15;
    if (!g_guide[bl & 7]) return;
    float* M = w ? &g_covs[bl][0][0] : &g_covc[bl][0][0];
    int t = threadIdx.x, lane = t & 31, warp = t >> 5;
    __shared__ __align__(16) float colk[256];
    __shared__ float diag;
    for (int k = 0; k < CC; k++) {
        if (t == 0) { float d = sqrtf(M[k*CC + k]); M[k*CC + k] = d; diag = d; }
        __syncthreads();
        float d = diag;
        float cv = 0.f;
        if (t > k) { cv = M[t*CC + k] / d; M[t*CC + k] = cv; }
        colk[t] = cv;
        __syncthreads();
        int q0 = (k + 1) >> 2;
        for (int i = k + 1 + warp; i < CC; i += 8) {
            float lik = colk[i];
            int qend = i >> 2;
            for (int q = q0 + lane; q <= qend; q += 32) {
                float4 mv = *(float4*)&M[i*CC + (q << 2)];
                float4 cq = *(const float4*)&colk[q << 2];
                mv.x -= lik * cq.x; mv.y -= lik * cq.y;
                mv.z -= lik * cq.z; mv.w -= lik * cq.w;
                *(float4*)&M[i*CC + (q << 2)] = mv;
            }
        }
        __syncthreads();
    }
}

// ---------------- 9. triangular inverse of L_c (column per thread) ----------------
__global__ __launch_bounds__(256) void k_inv() {
    int bl = blockIdx.x;
    if (!g_guide[bl & 7]) return;
    const float* L = &g_covc[bl][0][0];
    float*       X = &g_linv[bl][0][0];
    int j = threadIdx.x;
    float x[CC];
    for (int i = 0; i < CC; i++) {
        float v;
        if (i < j)      v = 0.f;
        else if (i == j) v = 1.f / L[i*CC + i];
        else {
            float s0 = 0.f, s1 = 0.f, s2 = 0.f, s3 = 0.f;
            const float* Lr = &L[i*CC];
            int k = j;
            for (; k + 4 <= i; k += 4) {
                s0 += Lr[k]   * x[k];
                s1 += Lr[k+1] * x[k+1];
                s2 += Lr[k+2] * x[k+2];
                s3 += Lr[k+3] * x[k+3];
            }
            for (; k < i; k++) s0 += Lr[k] * x[k];
            v = -((s0 + s1) + (s2 + s3)) / L[i*CC + i];
        }
        x[i] = v;
        X[i*CC + j] = v;
    }
}

// ---------------- 10. T = L_s * inv(L_c); corr = mu_s - T*mu_c ----------------
__global__ __launch_bounds__(256) void k_T() {
    int bl = blockIdx.y, c = blockIdx.x;
    int l = bl & 7, b = bl >> 3;
    if (!g_guide[l]) return;
    const float* Ls = &g_covs[bl][0][0];
    const float* Li = &g_linv[bl][0][0];
    float*       T  = &g_T[bl][0][0];
    int e = threadIdx.x;
    __shared__ float lsrow[CC];
    __shared__ float red[256];
    lsrow[e] = Ls[c*CC + e];
    __syncthreads();
    float s = 0.f;
    for (int d = e; d <= c; d++) s += lsrow[d] * Li[d*CC + e];
    T[c*CC + e] = s;                  // zero when e > c (empty loop)
    // corr reduction: sum_e T[c][e] * mu_c[e]
    red[e] = s * g_mean_c[b][l][e];
    __syncthreads();
    for (int q = 128; q > 0; q >>= 1) {
        if (e < q) red[e] += red[e + q];
        __syncthreads();
    }
    if (e == 0) g_corr[bl][c] = g_mean_s[b][l][c] - red[0];
}

// ---------------- 11. colored = T*x + corr, scatter into out (double-buffered) ----------------
__global__ __launch_bounds__(256) void k_color(float* __restrict__ out) {
    int bl = blockIdx.z; int l = bl & 7, b = bl >> 3;
    if (!g_guide[l]) return;
    int cnt = g_cnt_c[l];
    int j0  = blockIdx.x << 6;
    if (j0 >= cnt) return;
    int ri = blockIdx.y;
    int r0 = ri << 7;
    int kend = r0 + 128;              // T lower-triangular: cols >= kend are zero for these rows
    int off = g_off_c[l];
    const float* T   = &g_T[bl][0][0];
    const float* src = g_cg + ((long)b*CC) * NPIX;
    const float* corr = g_corr[bl];

    __shared__ __align__(16) float As[16][132];
    __shared__ __align__(16) float Bs[16][68];
    int t  = threadIdx.x;
    int tx = t & 15, ty = t >> 4;
    float acc[8][4];
    #pragma unroll
    for (int i = 0; i < 8; i++)
        #pragma unroll
        for (int j = 0; j < 4; j++) acc[i][j] = 0.f;

    int am  = t >> 1;                 // 0..127
    int ak0 = (t & 1) << 3;           // 0 or 8
    int bk  = t >> 4;                 // 0..15
    int bj  = (t & 15) << 2;

    const float* Trow = T + (long)(r0 + am)*CC + ak0;
    const float* brow = src + (long)bk*NPIX + off + j0 + bj;

    int niter = kend >> 4;
    float rT[8], rBv[4];
    {   // prologue kk = 0
        float4 t0 = *(const float4*)&Trow[0];
        float4 t1 = *(const float4*)&Trow[4];
        rT[0]=t0.x; rT[1]=t0.y; rT[2]=t0.z; rT[3]=t0.w;
        rT[4]=t1.x; rT[5]=t1.y; rT[6]=t1.z; rT[7]=t1.w;
        #pragma unroll
        for (int i = 0; i < 4; i++)
            rBv[i] = (j0 + bj + i < cnt) ? brow[i] : 0.f;
    }
    for (int it = 0; it < niter; it++) {
        #pragma unroll
        for (int i = 0; i < 8; i++) As[ak0 + i][am] = rT[i];
        #pragma unroll
        for (int i = 0; i < 4; i++) Bs[bk][bj + i] = rBv[i];
        __syncthreads();
        if (it + 1 < niter) {         // prefetch next K tile
            int kk = (it + 1) << 4;
            float4 t0 = *(const float4*)&Trow[kk];
            float4 t1 = *(const float4*)&Trow[kk + 4];
            rT[0]=t0.x; rT[1]=t0.y; rT[2]=t0.z; rT[3]=t0.w;
            rT[4]=t1.x; rT[5]=t1.y; rT[6]=t1.z; rT[7]=t1.w;
            const float* bp = brow + (long)kk*NPIX;
            #pragma unroll
            for (int i = 0; i < 4; i++)
                rBv[i] = (j0 + bj + i < cnt) ? bp[i] : 0.f;
        }
        #pragma unroll
        for (int k = 0; k < 16; k++) {
            float4 a0 = *(const float4*)&As[k][ty << 3];
            float4 a1 = *(const float4*)&As[k][(ty << 3) + 4];
            float4 b4 = *(const float4*)&Bs[k][tx << 2];
            float a[8]  = {a0.x, a0.y, a0.z, a0.w, a1.x, a1.y, a1.z, a1.w};
            float bv[4] = {b4.x, b4.y, b4.z, b4.w};
            #pragma unroll
            for (int i = 0; i < 8; i++)
                #pragma unroll
                for (int j = 0; j < 4; j++) acc[i][j] += a[i] * bv[j];
        }
        __syncthreads();
    }
    int jbase = j0 + (tx << 2);
    int pix[4];
    #pragma unroll
    for (int j = 0; j < 4; j++)
        pix[j] = (jbase + j < cnt) ? g_idx_c[off + jbase + j] : -1;
    #pragma unroll
    for (int i = 0; i < 8; i++) {
        int c = r0 + (ty << 3) + i;
        float cr = corr[c];
        long rowbase = ((long)(b*CC + c)) << 16;
        #pragma unroll
        for (int j = 0; j < 4; j++)
            if (pix[j] >= 0) out[rowbase + pix[j]] = acc[i][j] + cr;
    }
}

// ---------------- launcher ----------------
extern "C" void kernel_launch(void* const* d_in, const int* in_sizes, int n_in,
                              void* d_out, int out_size) {
    const float*        cf = (const float*)d_in[0];
    const float*        sf = (const float*)d_in[1];
    const unsigned int* cm = (const unsigned int*)d_in[2];
    const unsigned int* sm = (const unsigned int*)d_in[3];
    float* out = (float*)d_out;

    k_detect <<<1, 256>>>(cm, sm);
    k_hist   <<<NCHUNK, 256>>>(cm, sm);
    k_off    <<<1, 64>>>();
    k_scatter<<<NCHUNK, 256>>>();
    k_copy   <<<32768, 256>>>(cf, out);
    k_gather <<<dim3(32768, 2), 256>>>(cf, sf);
    k_sum    <<<dim3(CC, BB, 2), 256>>>();
    k_cov    <<<dim3(10, NBL, 2), 256>>>();
    k_chol   <<<32, 256>>>();
    k_inv    <<<16, 256>>>();
    k_T      <<<dim3(CC, NBL), 256>>>();
    k_color  <<<dim3(1024, 2, NBL), 256>>>(out);
}

// round 7
// speedup vs baseline: 1.2238x; 1.1088x over previous
#include <cuda_runtime.h>

#define BB 2
#define CC 256
#define NPIX 65536
#define NL 8
#define NCHUNK 256
#define NBL (BB*NL)
#define SPLITK 6

// ---------------- scratch (static device globals; no runtime allocation) ----------------
__device__ int g_is64_c, g_is64_s;
__device__ int g_hist_c[NCHUNK][NL];
__device__ int g_hist_s[NCHUNK][NL];
__device__ int g_base_c[NCHUNK][NL];
__device__ int g_base_s[NCHUNK][NL];
__device__ int g_off_c[NL+1];
__device__ int g_off_s[NL+1];
__device__ int g_cnt_c[NL];
__device__ int g_cnt_s[NL];
__device__ int g_guide[NL];
__device__ unsigned char g_lbl_c[NPIX];
__device__ unsigned char g_lbl_s[NPIX];
__device__ int g_idx_c[NPIX];
__device__ int g_idx_s[NPIX];
__device__ float g_mean_c[BB][NL][CC];
__device__ float g_mean_s[BB][NL][CC];
__device__ float g_corr[NBL][CC];         // mu_s - T*mu_c  (per bl, per out channel)
__device__ float g_cg[33554432];          // [B][C][N] content features, label-compacted (128 MB)
__device__ float g_sg[33554432];          // style, label-compacted (128 MB)
__device__ float g_covp[2][SPLITK][NBL][3][128][128]; // split-K SYRK partials (38 MB)
__device__ float g_covc[NBL][CC][CC];     // cov_c -> in-place Cholesky L_c
__device__ float g_covs[NBL][CC][CC];     // cov_s -> in-place Cholesky L_s
__device__ float g_linv[NBL][CC][CC];     // inv(L_c)
__device__ float g_T[NBL][CC][CC];        // T = L_s * inv(L_c)  (lower triangular)

__constant__ int c_PI[3] = {0,1,1};       // 128-row tile index per pair
__constant__ int c_PJ[3] = {0,0,1};       // 128-col tile index per pair

// ---------------- 0. mask dtype detection (int64 vs int32) ----------------
__global__ void k_detect(const unsigned int* __restrict__ cm, const unsigned int* __restrict__ sm) {
    __shared__ unsigned int oc[256], os[256];
    int t = threadIdx.x;
    unsigned int a = 0, b = 0;
    for (int i = t; i < 4096; i += 256) { a |= cm[2*i + 1]; b |= sm[2*i + 1]; }
    oc[t] = a; os[t] = b;
    __syncthreads();
    for (int s = 128; s > 0; s >>= 1) {
        if (t < s) { oc[t] |= oc[t + s]; os[t] |= os[t + s]; }
        __syncthreads();
    }
    if (t == 0) { g_is64_c = (oc[0] == 0); g_is64_s = (os[0] == 0); }
}

// ---------------- 1. per-chunk histograms + int8 label cache ----------------
__global__ void k_hist(const unsigned int* __restrict__ cm, const unsigned int* __restrict__ sm) {
    __shared__ int hc[NL], hs[NL];
    int t = threadIdx.x;
    if (t < NL) { hc[t] = 0; hs[t] = 0; }
    __syncthreads();
    int p = (blockIdx.x << 8) + t;
    int lc = (int)(g_is64_c ? cm[2*p] : cm[p]) & 7;
    int ls = (int)(g_is64_s ? sm[2*p] : sm[p]) & 7;
    g_lbl_c[p] = (unsigned char)lc;
    g_lbl_s[p] = (unsigned char)ls;
    atomicAdd(&hc[lc], 1);
    atomicAdd(&hs[ls], 1);
    __syncthreads();
    if (t < NL) { g_hist_c[blockIdx.x][t] = hc[t]; g_hist_s[blockIdx.x][t] = hs[t]; }
}

// ---------------- 2. totals, offsets, per-chunk bases, guide flags ----------------
__global__ void k_off() {
    int t = threadIdx.x;
    if (t < NL) {
        int run = 0;
        for (int ch = 0; ch < NCHUNK; ch++) { g_base_c[ch][t] = run; run += g_hist_c[ch][t]; }
        g_cnt_c[t] = run;
    } else if (t < 2*NL) {
        int l = t - NL; int run = 0;
        for (int ch = 0; ch < NCHUNK; ch++) { g_base_s[ch][l] = run; run += g_hist_s[ch][l]; }
        g_cnt_s[l] = run;
    }
    __syncthreads();
    if (t == 0) {
        int oc = 0, os = 0;
        for (int l = 0; l < NL; l++) {
            g_off_c[l] = oc; oc += g_cnt_c[l];
            g_off_s[l] = os; os += g_cnt_s[l];
        }
        g_off_c[NL] = oc; g_off_s[NL] = os;
        for (int l = 0; l < NL; l++) {
            long long a = g_cnt_c[l], b = g_cnt_s[l];
            g_guide[l] = (a > 10 && b > 10 && a < 10*b && b < 10*a) ? 1 : 0;
        }
    }
}

// ---------------- 3. stable counting-sort scatter (deterministic) ----------------
__global__ void k_scatter() {
    __shared__ unsigned char lc[256], ls[256];
    int t = threadIdx.x, ch = blockIdx.x;
    lc[t] = g_lbl_c[(ch << 8) + t];
    ls[t] = g_lbl_s[(ch << 8) + t];
    __syncthreads();
    if (t == 0) {
        int cur[NL];
        for (int l = 0; l < NL; l++) cur[l] = g_off_c[l] + g_base_c[ch][l];
        for (int i = 0; i < 256; i++) { int l = lc[i]; g_idx_c[cur[l]++] = (ch << 8) + i; }
    } else if (t == 32) {
        int cur[NL];
        for (int l = 0; l < NL; l++) cur[l] = g_off_s[l] + g_base_s[ch][l];
        for (int i = 0; i < 256; i++) { int l = ls[i]; g_idx_s[cur[l]++] = (ch << 8) + i; }
    }
}

// ---------------- 4. out = c_feat ----------------
__global__ void k_copy(const float* __restrict__ cf, float* __restrict__ out) {
    long i = ((long)blockIdx.x << 8) + threadIdx.x;
    ((float4*)out)[i] = ((const float4*)cf)[i];
}

// ---------------- 5. compact features by label order (vectorized) ----------------
__global__ void k_gather(const float* __restrict__ cf, const float* __restrict__ sf) {
    int which = blockIdx.y;
    long i4 = ((long)blockIdx.x << 8) + threadIdx.x;   // float4 index
    const int*   idx = which ? g_idx_s : g_idx_c;
    const float* f   = which ? sf      : cf;
    float*       dst = which ? g_sg    : g_cg;
    int  j4  = (int)(i4 & ((NPIX >> 2) - 1));
    long row = i4 >> 14;                                // NPIX/4 = 16384
    const int4 id = ((const int4*)idx)[j4];
    const float* fr = f + (row << 16);
    float4 v;
    v.x = fr[id.x]; v.y = fr[id.y]; v.z = fr[id.z]; v.w = fr[id.w];
    ((float4*)dst)[i4] = v;
}

// ---------------- 6. per-(b,label,channel) means from compacted segments ----------------
__global__ __launch_bounds__(256) void k_sum() {
    int c = blockIdx.x, b = blockIdx.y, w = blockIdx.z;
    const float* src = (w ? g_sg : g_cg) + ((long)(b*CC + c)) * NPIX;
    const int* off = w ? g_off_s : g_off_c;
    __shared__ float red[256];
    int t = threadIdx.x;
    for (int l = 0; l < NL; l++) {
        int lo = off[l], hi = off[l+1];
        float s = 0.f;
        for (int p = lo + t; p < hi; p += 256) s += src[p];
        red[t] = s;
        __syncthreads();
        for (int q = 128; q > 0; q >>= 1) {
            if (t < q) red[t] += red[t + q];
            __syncthreads();
        }
        if (t == 0) {
            int n = hi - lo;
            float m = (n > 0) ? red[0] / (float)n : 0.f;
            if (w) g_mean_s[b][l][c] = m; else g_mean_c[b][l][c] = m;
        }
        __syncthreads();
    }
}

// ---------------- 7a. raw SYRK partials: 128x128 tiles, 8x8/thread, split-K ----------------
__global__ __launch_bounds__(256, 2) void k_cov() {
    int tile  = blockIdx.x % 3;
    int chunk = blockIdx.x / 3;
    int bl = blockIdx.y;
    int w  = blockIdx.z;
    int l = bl & 7, b = bl >> 3;
    if (!g_guide[l]) return;
    int cnt = w ? g_cnt_s[l] : g_cnt_c[l];
    int off = w ? g_off_s[l] : g_off_c[l];
    const float* src = (w ? g_sg : g_cg) + ((long)b*CC) * NPIX;
    int ti = c_PI[tile], tj = c_PJ[tile];
    bool diag = (ti == tj);
    int k0 = (int)((long)cnt * chunk / SPLITK);
    int k1 = (int)((long)cnt * (chunk + 1) / SPLITK);

    __shared__ __align__(16) float As[16][132];
    __shared__ __align__(16) float Bs[16][132];
    int t  = threadIdx.x;
    int tx = t & 15, ty = t >> 4;
    int lk = t & 15, lm = (t >> 4) << 3;
    const float* pa = src + (long)(ti*128 + lm)*NPIX + off;
    const float* pb = src + (long)(tj*128 + lm)*NPIX + off;

    float acc[8][8];
    #pragma unroll
    for (int i = 0; i < 8; i++)
        #pragma unroll
        for (int j = 0; j < 8; j++) acc[i][j] = 0.f;

    int niter = (k1 - k0 + 15) >> 4;
    float rA[8], rB[8];
    {   // prologue: first tile -> regs
        int col = k0 + lk;
        bool ok = col < k1;
        #pragma unroll
        for (int i = 0; i < 8; i++) rA[i] = ok ? pa[(long)i*NPIX + col] : 0.f;
        if (!diag) {
            #pragma unroll
            for (int i = 0; i < 8; i++) rB[i] = ok ? pb[(long)i*NPIX + col] : 0.f;
        }
    }
    for (int it = 0; it < niter; it++) {
        #pragma unroll
        for (int i = 0; i < 8; i++) As[lk][lm + i] = rA[i];
        if (!diag) {
            #pragma unroll
            for (int i = 0; i < 8; i++) Bs[lk][lm + i] = rB[i];
        }
        __syncthreads();
        if (it + 1 < niter) {                 // prefetch next K tile
            int col = k0 + ((it + 1) << 4) + lk;
            bool ok = col < k1;
            #pragma unroll
            for (int i = 0; i < 8; i++) rA[i] = ok ? pa[(long)i*NPIX + col] : 0.f;
            if (!diag) {
                #pragma unroll
                for (int i = 0; i < 8; i++) rB[i] = ok ? pb[(long)i*NPIX + col] : 0.f;
            }
        }
        float (*Bp)[132] = diag ? As : Bs;
        #pragma unroll
        for (int k = 0; k < 16; k++) {
            float4 a0 = *(const float4*)&As[k][ty << 3];
            float4 a1 = *(const float4*)&As[k][(ty << 3) + 4];
            float4 b0 = *(const float4*)&Bp[k][tx << 3];
            float4 b1 = *(const float4*)&Bp[k][(tx << 3) + 4];
            float a[8]  = {a0.x, a0.y, a0.z, a0.w, a1.x, a1.y, a1.z, a1.w};
            float bv[8] = {b0.x, b0.y, b0.z, b0.w, b1.x, b1.y, b1.z, b1.w};
            #pragma unroll
            for (int i = 0; i < 8; i++)
                #pragma unroll
                for (int j = 0; j < 8; j++) acc[i][j] += a[i] * bv[j];
        }
        __syncthreads();
    }
    float* dst = &g_covp[w][chunk][bl][tile][0][0];
    #pragma unroll
    for (int i = 0; i < 8; i++) {
        float4 v0 = {acc[i][0], acc[i][1], acc[i][2], acc[i][3]};
        float4 v1 = {acc[i][4], acc[i][5], acc[i][6], acc[i][7]};
        int r = (ty << 3) + i;
        *(float4*)&dst[r*128 + (tx << 3)]     = v0;
        *(float4*)&dst[r*128 + (tx << 3) + 4] = v1;
    }
}

// ---------------- 7b. reduce split-K partials + rank-1 mean correction + mirror ----------------
__global__ __launch_bounds__(256) void k_covred() {
    int w = blockIdx.z;
    int tile = blockIdx.y % 3, bl = blockIdx.y / 3;
    int l = bl & 7, b = bl >> 3;
    if (!g_guide[l]) return;
    int idx = (blockIdx.x << 8) + threadIdx.x;   // 0..16383
    int r = idx >> 7, c = idx & 127;
    int ti = c_PI[tile], tj = c_PJ[tile];
    int gr = ti*128 + r, gc = tj*128 + c;
    float s = 0.f;
    #pragma unroll
    for (int ch = 0; ch < SPLITK; ch++) s += g_covp[w][ch][bl][tile][r][c];
    int cnt = w ? g_cnt_s[l] : g_cnt_c[l];
    const float* mean = w ? g_mean_s[b][l] : g_mean_c[b][l];
    float a = (float)cnt;
    float v = (s - a * mean[gr] * mean[gc]) / (a - 1.f);
    float (*cov)[CC] = w ? g_covs[bl] : g_covc[bl];
    cov[gr][gc] = v;
    if (tile == 1) cov[gc][gr] = v;
}

// ---------------- 8. in-place right-looking Cholesky (32 matrices) ----------------
__global__ __launch_bounds__(256) void k_chol() {
    int w = blockIdx.x >> 4, bl = blockIdx.x & 15;
    if (!g_guide[bl & 7]) return;
    float* M = w ? &g_covs[bl][0][0] : &g_covc[bl][0][0];
    int t = threadIdx.x, lane = t & 31, warp = t >> 5;
    __shared__ __align__(16) float colk[256];
    __shared__ float diag;
    for (int k = 0; k < CC; k++) {
        if (t == 0) { float d = sqrtf(M[k*CC + k]); M[k*CC + k] = d; diag = d; }
        __syncthreads();
        float d = diag;
        float cv = 0.f;
        if (t > k) { cv = M[t*CC + k] / d; M[t*CC + k] = cv; }
        colk[t] = cv;
        __syncthreads();
        int q0 = (k + 1) >> 2;
        for (int i = k + 1 + warp; i < CC; i += 8) {
            float lik = colk[i];
            int qend = i >> 2;
            for (int q = q0 + lane; q <= qend; q += 32) {
                float4 mv = *(float4*)&M[i*CC + (q << 2)];
                float4 cq = *(const float4*)&colk[q << 2];
                mv.x -= lik * cq.x; mv.y -= lik * cq.y;
                mv.z -= lik * cq.z; mv.w -= lik * cq.w;
                *(float4*)&M[i*CC + (q << 2)] = mv;
            }
        }
        __syncthreads();
    }
}

// ---------------- 9. triangular inverse of L_c (column per thread) ----------------
__global__ __launch_bounds__(256) void k_inv() {
    int bl = blockIdx.x;
    if (!g_guide[bl & 7]) return;
    const float* L = &g_covc[bl][0][0];
    float*       X = &g_linv[bl][0][0];
    int j = threadIdx.x;
    float x[CC];
    for (int i = 0; i < CC; i++) {
        float v;
        if (i < j)      v = 0.f;
        else if (i == j) v = 1.f / L[i*CC + i];
        else {
            float s0 = 0.f, s1 = 0.f, s2 = 0.f, s3 = 0.f;
            const float* Lr = &L[i*CC];
            int k = j;
            for (; k + 4 <= i; k += 4) {
                s0 += Lr[k]   * x[k];
                s1 += Lr[k+1] * x[k+1];
                s2 += Lr[k+2] * x[k+2];
                s3 += Lr[k+3] * x[k+3];
            }
            for (; k < i; k++) s0 += Lr[k] * x[k];
            v = -((s0 + s1) + (s2 + s3)) / L[i*CC + i];
        }
        x[i] = v;
        X[i*CC + j] = v;
    }
}

// ---------------- 10. T = L_s * inv(L_c); corr = mu_s - T*mu_c ----------------
__global__ __launch_bounds__(256) void k_T() {
    int bl = blockIdx.y, c = blockIdx.x;
    int l = bl & 7, b = bl >> 3;
    if (!g_guide[l]) return;
    const float* Ls = &g_covs[bl][0][0];
    const float* Li = &g_linv[bl][0][0];
    float*       T  = &g_T[bl][0][0];
    int e = threadIdx.x;
    __shared__ float lsrow[CC];
    __shared__ float red[256];
    lsrow[e] = Ls[c*CC + e];
    __syncthreads();
    float s = 0.f;
    for (int d = e; d <= c; d++) s += lsrow[d] * Li[d*CC + e];
    T[c*CC + e] = s;                  // zero when e > c (empty loop)
    red[e] = s * g_mean_c[b][l][e];
    __syncthreads();
    for (int q = 128; q > 0; q >>= 1) {
        if (e < q) red[e] += red[e + q];
        __syncthreads();
    }
    if (e == 0) g_corr[bl][c] = g_mean_s[b][l][c] - red[0];
}

// ---------------- 11. colored = T*x + corr, scatter into out (double-buffered) ----------------
__global__ __launch_bounds__(256) void k_color(float* __restrict__ out) {
    int bl = blockIdx.z; int l = bl & 7, b = bl >> 3;
    if (!g_guide[l]) return;
    int cnt = g_cnt_c[l];
    int j0  = blockIdx.x << 6;
    if (j0 >= cnt) return;
    int ri = blockIdx.y;
    int r0 = ri << 7;
    int kend = r0 + 128;              // T lower-triangular: cols >= kend are zero for these rows
    int off = g_off_c[l];
    const float* T   = &g_T[bl][0][0];
    const float* src = g_cg + ((long)b*CC) * NPIX;
    const float* corr = g_corr[bl];

    __shared__ __align__(16) float As[16][132];
    __shared__ __align__(16) float Bs[16][68];
    int t  = threadIdx.x;
    int tx = t & 15, ty = t >> 4;
    float acc[8][4];
    #pragma unroll
    for (int i = 0; i < 8; i++)
        #pragma unroll
        for (int j = 0; j < 4; j++) acc[i][j] = 0.f;

    int am  = t >> 1;                 // 0..127
    int ak0 = (t & 1) << 3;           // 0 or 8
    int bk  = t >> 4;                 // 0..15
    int bj  = (t & 15) << 2;

    const float* Trow = T + (long)(r0 + am)*CC + ak0;
    const float* brow = src + (long)bk*NPIX + off + j0 + bj;

    int niter = kend >> 4;
    float rT[8], rBv[4];
    {   // prologue kk = 0
        float4 t0 = *(const float4*)&Trow[0];
        float4 t1 = *(const float4*)&Trow[4];
        rT[0]=t0.x; rT[1]=t0.y; rT[2]=t0.z; rT[3]=t0.w;
        rT[4]=t1.x; rT[5]=t1.y; rT[6]=t1.z; rT[7]=t1.w;
        #pragma unroll
        for (int i = 0; i < 4; i++)
            rBv[i] = (j0 + bj + i < cnt) ? brow[i] : 0.f;
    }
    for (int it = 0; it < niter; it++) {
        #pragma unroll
        for (int i = 0; i < 8; i++) As[ak0 + i][am] = rT[i];
        #pragma unroll
        for (int i = 0; i < 4; i++) Bs[bk][bj + i] = rBv[i];
        __syncthreads();
        if (it + 1 < niter) {         // prefetch next K tile
            int kk = (it + 1) << 4;
            float4 t0 = *(const float4*)&Trow[kk];
            float4 t1 = *(const float4*)&Trow[kk + 4];
            rT[0]=t0.x; rT[1]=t0.y; rT[2]=t0.z; rT[3]=t0.w;
            rT[4]=t1.x; rT[5]=t1.y; rT[6]=t1.z; rT[7]=t1.w;
            const float* bp = brow + (long)kk*NPIX;
            #pragma unroll
            for (int i = 0; i < 4; i++)
                rBv[i] = (j0 + bj + i < cnt) ? bp[i] : 0.f;
        }
        #pragma unroll
        for (int k = 0; k < 16; k++) {
            float4 a0 = *(const float4*)&As[k][ty << 3];
            float4 a1 = *(const float4*)&As[k][(ty << 3) + 4];
            float4 b4 = *(const float4*)&Bs[k][tx << 2];
            float a[8]  = {a0.x, a0.y, a0.z, a0.w, a1.x, a1.y, a1.z, a1.w};
            float bv[4] = {b4.x, b4.y, b4.z, b4.w};
            #pragma unroll
            for (int i = 0; i < 8; i++)
                #pragma unroll
                for (int j = 0; j < 4; j++) acc[i][j] += a[i] * bv[j];
        }
        __syncthreads();
    }
    int jbase = j0 + (tx << 2);
    int pix[4];
    #pragma unroll
    for (int j = 0; j < 4; j++)
        pix[j] = (jbase + j < cnt) ? g_idx_c[off + jbase + j] : -1;
    #pragma unroll
    for (int i = 0; i < 8; i++) {
        int c = r0 + (ty << 3) + i;
        float cr = corr[c];
        long rowbase = ((long)(b*CC + c)) << 16;
        #pragma unroll
        for (int j = 0; j < 4; j++)
            if (pix[j] >= 0) out[rowbase + pix[j]] = acc[i][j] + cr;
    }
}

// ---------------- launcher ----------------
extern "C" void kernel_launch(void* const* d_in, const int* in_sizes, int n_in,
                              void* d_out, int out_size) {
    const float*        cf = (const float*)d_in[0];
    const float*        sf = (const float*)d_in[1];
    const unsigned int* cm = (const unsigned int*)d_in[2];
    const unsigned int* sm = (const unsigned int*)d_in[3];
    float* out = (float*)d_out;

    k_detect <<<1, 256>>>(cm, sm);
    k_hist   <<<NCHUNK, 256>>>(cm, sm);
    k_off    <<<1, 64>>>();
    k_scatter<<<NCHUNK, 256>>>();
    k_copy   <<<32768, 256>>>(cf, out);
    k_gather <<<dim3(32768, 2), 256>>>(cf, sf);
    k_sum    <<<dim3(CC, BB, 2), 256>>>();
    k_cov    <<<dim3(3*SPLITK, NBL, 2), 256>>>();
    k_covred <<<dim3(64, 3*NBL, 2), 256>>>();
    k_chol   <<<32, 256>>>();
    k_inv    <<<16, 256>>>();
    k_T      <<<dim3(CC, NBL), 256>>>();
    k_color  <<<dim3(1024, 2, NBL), 256>>>(out);
}

// round 9
// speedup vs baseline: 1.2489x; 1.0205x over previous
#include <cuda_runtime.h>

#define BB 2
#define CC 256
#define NPIX 65536
#define NL 8
#define NCHUNK 256
#define NBL (BB*NL)
#define SPLITK 6

// ---------------- f32x2 packed-FMA helpers (FFMA2 — only reachable via PTX) ----------------
__device__ __forceinline__ unsigned long long pk2(float x) {
    unsigned long long r;
    asm("mov.b64 %0, {%1, %1};" : "=l"(r) : "f"(x));
    return r;
}
__device__ __forceinline__ void upk2(unsigned long long v, float &lo, float &hi) {
    asm("mov.b64 {%0, %1}, %2;" : "=f"(lo), "=f"(hi) : "l"(v));
}
__device__ __forceinline__ void ffma2(unsigned long long &d, unsigned long long a, unsigned long long b) {
    asm("fma.rn.f32x2 %0, %1, %2, %0;" : "+l"(d) : "l"(a), "l"(b));
}

// ---------------- scratch (static device globals; no runtime allocation) ----------------
__device__ int g_is64_c, g_is64_s;
__device__ int g_hist_c[NCHUNK][NL];
__device__ int g_hist_s[NCHUNK][NL];
__device__ int g_base_c[NCHUNK][NL];
__device__ int g_base_s[NCHUNK][NL];
__device__ int g_off_c[NL+1];
__device__ int g_off_s[NL+1];
__device__ int g_cnt_c[NL];
__device__ int g_cnt_s[NL];
__device__ int g_guide[NL];
__device__ int g_ctile[NL+1];             // per-label prefix of 64-wide j tiles (guided only)
__device__ unsigned char g_lbl_c[NPIX];
__device__ unsigned char g_lbl_s[NPIX];
__device__ int g_idx_c[NPIX];
__device__ int g_idx_s[NPIX];
__device__ float g_mean_c[BB][NL][CC];
__device__ float g_mean_s[BB][NL][CC];
__device__ float g_corr[NBL][CC];         // mu_s - T*mu_c  (per bl, per out channel)
__device__ float g_cg[33554432];          // [B][C][N] content features, label-compacted (128 MB)
__device__ float g_sg[33554432];          // style, label-compacted (128 MB)
__device__ float g_covp[2][SPLITK][NBL][3][128][128]; // split-K SYRK partials (38 MB)
__device__ float g_covc[NBL][CC][CC];     // cov_c -> in-place Cholesky L_c
__device__ float g_covs[NBL][CC][CC];     // cov_s -> in-place Cholesky L_s
__device__ float g_linv[NBL][CC][CC];     // inv(L_c)
__device__ float g_T[NBL][CC][CC];        // T = L_s * inv(L_c)  (lower triangular)

__constant__ int c_PI[3] = {0,1,1};       // 128-row tile index per pair
__constant__ int c_PJ[3] = {0,0,1};       // 128-col tile index per pair

// ---------------- 0. mask dtype detection (int64 vs int32) ----------------
__global__ void k_detect(const unsigned int* __restrict__ cm, const unsigned int* __restrict__ sm) {
    __shared__ unsigned int oc[256], os[256];
    int t = threadIdx.x;
    unsigned int a = 0, b = 0;
    for (int i = t; i < 4096; i += 256) { a |= cm[2*i + 1]; b |= sm[2*i + 1]; }
    oc[t] = a; os[t] = b;
    __syncthreads();
    for (int s = 128; s > 0; s >>= 1) {
        if (t < s) { oc[t] |= oc[t + s]; os[t] |= os[t + s]; }
        __syncthreads();
    }
    if (t == 0) { g_is64_c = (oc[0] == 0); g_is64_s = (os[0] == 0); }
}

// ---------------- 1. per-chunk histograms + int8 label cache ----------------
__global__ void k_hist(const unsigned int* __restrict__ cm, const unsigned int* __restrict__ sm) {
    __shared__ int hc[NL], hs[NL];
    int t = threadIdx.x;
    if (t < NL) { hc[t] = 0; hs[t] = 0; }
    __syncthreads();
    int p = (blockIdx.x << 8) + t;
    int lc = (int)(g_is64_c ? cm[2*p] : cm[p]) & 7;
    int ls = (int)(g_is64_s ? sm[2*p] : sm[p]) & 7;
    g_lbl_c[p] = (unsigned char)lc;
    g_lbl_s[p] = (unsigned char)ls;
    atomicAdd(&hc[lc], 1);
    atomicAdd(&hs[ls], 1);
    __syncthreads();
    if (t < NL) { g_hist_c[blockIdx.x][t] = hc[t]; g_hist_s[blockIdx.x][t] = hs[t]; }
}

// ---------------- 2. totals, offsets, per-chunk bases, guide flags, color tiles ----------------
__global__ void k_off() {
    int t = threadIdx.x;
    if (t < NL) {
        int run = 0;
        for (int ch = 0; ch < NCHUNK; ch++) { g_base_c[ch][t] = run; run += g_hist_c[ch][t]; }
        g_cnt_c[t] = run;
    } else if (t < 2*NL) {
        int l = t - NL; int run = 0;
        for (int ch = 0; ch < NCHUNK; ch++) { g_base_s[ch][l] = run; run += g_hist_s[ch][l]; }
        g_cnt_s[l] = run;
    }
    __syncthreads();
    if (t == 0) {
        int oc = 0, os = 0;
        for (int l = 0; l < NL; l++) {
            g_off_c[l] = oc; oc += g_cnt_c[l];
            g_off_s[l] = os; os += g_cnt_s[l];
        }
        g_off_c[NL] = oc; g_off_s[NL] = os;
        int tp = 0;
        for (int l = 0; l < NL; l++) {
            long long a = g_cnt_c[l], b = g_cnt_s[l];
            int gd = (a > 10 && b > 10 && a < 10*b && b < 10*a) ? 1 : 0;
            g_guide[l] = gd;
            g_ctile[l] = tp;
            if (gd) tp += (g_cnt_c[l] + 63) >> 6;
        }
        g_ctile[NL] = tp;
    }
}

// ---------------- 3. stable counting-sort scatter (deterministic) ----------------
__global__ void k_scatter() {
    __shared__ unsigned char lc[256], ls[256];
    int t = threadIdx.x, ch = blockIdx.x;
    lc[t] = g_lbl_c[(ch << 8) + t];
    ls[t] = g_lbl_s[(ch << 8) + t];
    __syncthreads();
    if (t == 0) {
        int cur[NL];
        for (int l = 0; l < NL; l++) cur[l] = g_off_c[l] + g_base_c[ch][l];
        for (int i = 0; i < 256; i++) { int l = lc[i]; g_idx_c[cur[l]++] = (ch << 8) + i; }
    } else if (t == 32) {
        int cur[NL];
        for (int l = 0; l < NL; l++) cur[l] = g_off_s[l] + g_base_s[ch][l];
        for (int i = 0; i < 256; i++) { int l = ls[i]; g_idx_s[cur[l]++] = (ch << 8) + i; }
    }
}

// ---------------- 4. out = c_feat ----------------
__global__ void k_copy(const float* __restrict__ cf, float* __restrict__ out) {
    long i = ((long)blockIdx.x << 8) + threadIdx.x;
    ((float4*)out)[i] = ((const float4*)cf)[i];
}

// ---------------- 5. compact features by label order (vectorized) ----------------
__global__ void k_gather(const float* __restrict__ cf, const float* __restrict__ sf) {
    int which = blockIdx.y;
    long i4 = ((long)blockIdx.x << 8) + threadIdx.x;   // float4 index
    const int*   idx = which ? g_idx_s : g_idx_c;
    const float* f   = which ? sf      : cf;
    float*       dst = which ? g_sg    : g_cg;
    int  j4  = (int)(i4 & ((NPIX >> 2) - 1));
    long row = i4 >> 14;                                // NPIX/4 = 16384
    const int4 id = ((const int4*)idx)[j4];
    const float* fr = f + (row << 16);
    float4 v;
    v.x = fr[id.x]; v.y = fr[id.y]; v.z = fr[id.z]; v.w = fr[id.w];
    ((float4*)dst)[i4] = v;
}

// ---------------- 6. per-(b,label,channel) means from compacted segments ----------------
__global__ __launch_bounds__(256) void k_sum() {
    int c = blockIdx.x, b = blockIdx.y, w = blockIdx.z;
    const float* src = (w ? g_sg : g_cg) + ((long)(b*CC + c)) * NPIX;
    const int* off = w ? g_off_s : g_off_c;
    __shared__ float red[256];
    int t = threadIdx.x;
    for (int l = 0; l < NL; l++) {
        int lo = off[l], hi = off[l+1];
        float s = 0.f;
        for (int p = lo + t; p < hi; p += 256) s += src[p];
        red[t] = s;
        __syncthreads();
        for (int q = 128; q > 0; q >>= 1) {
            if (t < q) red[t] += red[t + q];
            __syncthreads();
        }
        if (t == 0) {
            int n = hi - lo;
            float m = (n > 0) ? red[0] / (float)n : 0.f;
            if (w) g_mean_s[b][l][c] = m; else g_mean_c[b][l][c] = m;
        }
        __syncthreads();
    }
}

// ---------------- 7a. raw SYRK partials: 128x128 tiles, FFMA2, split-K ----------------
__global__ __launch_bounds__(256, 2) void k_cov() {
    int tile  = blockIdx.x % 3;
    int chunk = blockIdx.x / 3;
    int bl = blockIdx.y;
    int w  = blockIdx.z;
    int l = bl & 7, b = bl >> 3;
    if (!g_guide[l]) return;
    int cnt = w ? g_cnt_s[l] : g_cnt_c[l];
    int off = w ? g_off_s[l] : g_off_c[l];
    const float* src = (w ? g_sg : g_cg) + ((long)b*CC) * NPIX;
    int ti = c_PI[tile], tj = c_PJ[tile];
    bool diag = (ti == tj);
    int k0 = (int)((long)cnt * chunk / SPLITK);
    int k1 = (int)((long)cnt * (chunk + 1) / SPLITK);

    __shared__ __align__(16) float As[16][132];
    __shared__ __align__(16) float Bs[16][132];
    int t  = threadIdx.x;
    int tx = t & 15, ty = t >> 4;
    int lk = t & 15, lm = (t >> 4) << 3;
    const float* pa = src + (long)(ti*128 + lm)*NPIX + off;
    const float* pb = src + (long)(tj*128 + lm)*NPIX + off;

    unsigned long long acc2[4][8];     // row-pairs (2i,2i+1) x 8 cols
    #pragma unroll
    for (int i = 0; i < 4; i++)
        #pragma unroll
        for (int j = 0; j < 8; j++) acc2[i][j] = 0ull;

    int niter = (k1 - k0 + 15) >> 4;
    float rA[8], rB[8];
    {   // prologue: first tile -> regs
        int col = k0 + lk;
        bool ok = col < k1;
        #pragma unroll
        for (int i = 0; i < 8; i++) rA[i] = ok ? pa[(long)i*NPIX + col] : 0.f;
        if (!diag) {
            #pragma unroll
            for (int i = 0; i < 8; i++) rB[i] = ok ? pb[(long)i*NPIX + col] : 0.f;
        }
    }
    for (int it = 0; it < niter; it++) {
        #pragma unroll
        for (int i = 0; i < 8; i++) As[lk][lm + i] = rA[i];
        if (!diag) {
            #pragma unroll
            for (int i = 0; i < 8; i++) Bs[lk][lm + i] = rB[i];
        }
        __syncthreads();
        if (it + 1 < niter) {                 // prefetch next K tile
            int col = k0 + ((it + 1) << 4) + lk;
            bool ok = col < k1;
            #pragma unroll
            for (int i = 0; i < 8; i++) rA[i] = ok ? pa[(long)i*NPIX + col] : 0.f;
            if (!diag) {
                #pragma unroll
                for (int i = 0; i < 8; i++) rB[i] = ok ? pb[(long)i*NPIX + col] : 0.f;
            }
        }
        float (*Bp)[132] = diag ? As : Bs;
        #pragma unroll
        for (int k = 0; k < 16; k++) {
            ulonglong2 av0 = *(const ulonglong2*)&As[k][ty << 3];
            ulonglong2 av1 = *(const ulonglong2*)&As[k][(ty << 3) + 4];
            unsigned long long a2[4] = {av0.x, av0.y, av1.x, av1.y};
            float4 b0 = *(const float4*)&Bp[k][tx << 3];
            float4 b1 = *(const float4*)&Bp[k][(tx << 3) + 4];
            float bv[8] = {b0.x, b0.y, b0.z, b0.w, b1.x, b1.y, b1.z, b1.w};
            #pragma unroll
            for (int j = 0; j < 8; j++) {
                unsigned long long bd = pk2(bv[j]);
                #pragma unroll
                for (int i = 0; i < 4; i++) ffma2(acc2[i][j], a2[i], bd);
            }
        }
        __syncthreads();
    }
    float accf[8][8];
    #pragma unroll
    for (int i = 0; i < 4; i++)
        #pragma unroll
        for (int j = 0; j < 8; j++) upk2(acc2[i][j], accf[2*i][j], accf[2*i + 1][j]);
    float* dst = &g_covp[w][chunk][bl][tile][0][0];
    #pragma unroll
    for (int i = 0; i < 8; i++) {
        float4 v0 = {accf[i][0], accf[i][1], accf[i][2], accf[i][3]};
        float4 v1 = {accf[i][4], accf[i][5], accf[i][6], accf[i][7]};
        int r = (ty << 3) + i;
        *(float4*)&dst[r*128 + (tx << 3)]     = v0;
        *(float4*)&dst[r*128 + (tx << 3) + 4] = v1;
    }
}

// ---------------- 7b. reduce split-K partials + rank-1 mean correction + mirror ----------------
__global__ __launch_bounds__(256) void k_covred() {
    int w = blockIdx.z;
    int tile = blockIdx.y % 3, bl = blockIdx.y / 3;
    int l = bl & 7, b = bl >> 3;
    if (!g_guide[l]) return;
    int idx = (blockIdx.x << 8) + threadIdx.x;   // 0..16383
    int r = idx >> 7, c = idx & 127;
    int ti = c_PI[tile], tj = c_PJ[tile];
    int gr = ti*128 + r, gc = tj*128 + c;
    float s = 0.f;
    #pragma unroll
    for (int ch = 0; ch < SPLITK; ch++) s += g_covp[w][ch][bl][tile][r][c];
    int cnt = w ? g_cnt_s[l] : g_cnt_c[l];
    const float* mean = w ? g_mean_s[b][l] : g_mean_c[b][l];
    float a = (float)cnt;
    float v = (s - a * mean[gr] * mean[gc]) / (a - 1.f);
    float (*cov)[CC] = w ? g_covs[bl] : g_covc[bl];
    cov[gr][gc] = v;
    if (tile == 1) cov[gc][gr] = v;
}

// ---------------- 8. in-place right-looking Cholesky (32 matrices) ----------------
__global__ __launch_bounds__(256) void k_chol() {
    int w = blockIdx.x >> 4, bl = blockIdx.x & 15;
    if (!g_guide[bl & 7]) return;
    float* M = w ? &g_covs[bl][0][0] : &g_covc[bl][0][0];
    int t = threadIdx.x, lane = t & 31, warp = t >> 5;
    __shared__ __align__(16) float colk[256];
    __shared__ float diag;
    for (int k = 0; k < CC; k++) {
        if (t == 0) { float d = sqrtf(M[k*CC + k]); M[k*CC + k] = d; diag = d; }
        __syncthreads();
        float d = diag;
        float cv = 0.f;
        if (t > k) { cv = M[t*CC + k] / d; M[t*CC + k] = cv; }
        colk[t] = cv;
        __syncthreads();
        int q0 = (k + 1) >> 2;
        for (int i = k + 1 + warp; i < CC; i += 8) {
            float lik = colk[i];
            int qend = i >> 2;
            for (int q = q0 + lane; q <= qend; q += 32) {
                float4 mv = *(float4*)&M[i*CC + (q << 2)];
                float4 cq = *(const float4*)&colk[q << 2];
                mv.x -= lik * cq.x; mv.y -= lik * cq.y;
                mv.z -= lik * cq.z; mv.w -= lik * cq.w;
                *(float4*)&M[i*CC + (q << 2)] = mv;
            }
        }
        __syncthreads();
    }
}

// ---------------- 9. triangular inverse of L_c (column per thread) ----------------
__global__ __launch_bounds__(256) void k_inv() {
    int bl = blockIdx.x;
    if (!g_guide[bl & 7]) return;
    const float* L = &g_covc[bl][0][0];
    float*       X = &g_linv[bl][0][0];
    int j = threadIdx.x;
    float x[CC];
    for (int i = 0; i < CC; i++) {
        float v;
        if (i < j)      v = 0.f;
        else if (i == j) v = 1.f / L[i*CC + i];
        else {
            float s0 = 0.f, s1 = 0.f, s2 = 0.f, s3 = 0.f;
            const float* Lr = &L[i*CC];
            int k = j;
            for (; k + 4 <= i; k += 4) {
                s0 += Lr[k]   * x[k];
                s1 += Lr[k+1] * x[k+1];
                s2 += Lr[k+2] * x[k+2];
                s3 += Lr[k+3] * x[k+3];
            }
            for (; k < i; k++) s0 += Lr[k] * x[k];
            v = -((s0 + s1) + (s2 + s3)) / L[i*CC + i];
        }
        x[i] = v;
        X[i*CC + j] = v;
    }
}

// ---------------- 10. T = L_s * inv(L_c); corr = mu_s - T*mu_c ----------------
__global__ __launch_bounds__(256) void k_T() {
    int bl = blockIdx.y, c = blockIdx.x;
    int l = bl & 7, b = bl >> 3;
    if (!g_guide[l]) return;
    const float* Ls = &g_covs[bl][0][0];
    const float* Li = &g_linv[bl][0][0];
    float*       T  = &g_T[bl][0][0];
    int e = threadIdx.x;
    __shared__ float lsrow[CC];
    __shared__ float red[256];
    lsrow[e] = Ls[c*CC + e];
    __syncthreads();
    float s = 0.f;
    for (int d = e; d <= c; d++) s += lsrow[d] * Li[d*CC + e];
    T[c*CC + e] = s;                  // zero when e > c (empty loop)
    red[e] = s * g_mean_c[b][l][e];
    __syncthreads();
    for (int q = 128; q > 0; q >>= 1) {
        if (e < q) red[e] += red[e + q];
        __syncthreads();
    }
    if (e == 0) g_corr[bl][c] = g_mean_s[b][l][c] - red[0];
}

// ---------------- 11. colored = T*x + corr, scatter into out (FFMA2, tight grid) ----------------
__global__ __launch_bounds__(256) void k_color(float* __restrict__ out) {
    int bx = blockIdx.x;
    if (bx >= g_ctile[NL]) return;
    int l = 0;
    for (; l < NL-1 && bx >= g_ctile[l+1]; l++);
    int b  = blockIdx.z;
    int bl = b*8 + l;
    int cnt = g_cnt_c[l];
    int j0  = (bx - g_ctile[l]) << 6;
    int ri = blockIdx.y;
    int r0 = ri << 7;
    int kend = r0 + 128;              // T lower-triangular: cols >= kend are zero for these rows
    int off = g_off_c[l];
    const float* T   = &g_T[bl][0][0];
    const float* src = g_cg + ((long)b*CC) * NPIX;
    const float* corr = g_corr[bl];

    __shared__ __align__(16) float As[16][132];
    __shared__ __align__(16) float Bs[16][68];
    int t  = threadIdx.x;
    int tx = t & 15, ty = t >> 4;
    unsigned long long acc2[4][4];     // row-pairs x 4 cols
    #pragma unroll
    for (int i = 0; i < 4; i++)
        #pragma unroll
        for (int j = 0; j < 4; j++) acc2[i][j] = 0ull;

    int am  = t >> 1;                 // 0..127
    int ak0 = (t & 1) << 3;           // 0 or 8
    int bk  = t >> 4;                 // 0..15
    int bj  = (t & 15) << 2;

    const float* Trow = T + (long)(r0 + am)*CC + ak0;
    const float* brow = src + (long)bk*NPIX + off + j0 + bj;

    int niter = kend >> 4;
    float rT[8], rBv[4];
    {   // prologue kk = 0
        float4 t0 = *(const float4*)&Trow[0];
        float4 t1 = *(const float4*)&Trow[4];
        rT[0]=t0.x; rT[1]=t0.y; rT[2]=t0.z; rT[3]=t0.w;
        rT[4]=t1.x; rT[5]=t1.y; rT[6]=t1.z; rT[7]=t1.w;
        #pragma unroll
        for (int i = 0; i < 4; i++)
            rBv[i] = (j0 + bj + i < cnt) ? brow[i] : 0.f;
    }
    for (int it = 0; it < niter; it++) {
        #pragma unroll
        for (int i = 0; i < 8; i++) As[ak0 + i][am] = rT[i];
        #pragma unroll
        for (int i = 0; i < 4; i++) Bs[bk][bj + i] = rBv[i];
        __syncthreads();
        if (it + 1 < niter) {         // prefetch next K tile
            int kk = (it + 1) << 4;
            float4 t0 = *(const float4*)&Trow[kk];
            float4 t1 = *(const float4*)&Trow[kk + 4];
            rT[0]=t0.x; rT[1]=t0.y; rT[2]=t0.z; rT[3]=t0.w;
            rT[4]=t1.x; rT[5]=t1.y; rT[6]=t1.z; rT[7]=t1.w;
            const float* bp = brow + (long)kk*NPIX;
            #pragma unroll
            for (int i = 0; i < 4; i++)
                rBv[i] = (j0 + bj + i < cnt) ? bp[i] : 0.f;
        }
        #pragma unroll
        for (int k = 0; k < 16; k++) {
            ulonglong2 av0 = *(const ulonglong2*)&As[k][ty << 3];
            ulonglong2 av1 = *(const ulonglong2*)&As[k][(ty << 3) + 4];
            unsigned long long a2[4] = {av0.x, av0.y, av1.x, av1.y};
            float4 b4 = *(const float4*)&Bs[k][tx << 2];
            float bv[4] = {b4.x, b4.y, b4.z, b4.w};
            #pragma unroll
            for (int j = 0; j < 4; j++) {
                unsigned long long bd = pk2(bv[j]);
                #pragma unroll
                for (int i = 0; i < 4; i++) ffma2(acc2[i][j], a2[i], bd);
            }
        }
        __syncthreads();
    }
    float accf[8][4];
    #pragma unroll
    for (int i = 0; i < 4; i++)
        #pragma unroll
        for (int j = 0; j < 4; j++) upk2(acc2[i][j], accf[2*i][j], accf[2*i + 1][j]);
    int jbase = j0 + (tx << 2);
    int pix[4];
    #pragma unroll
    for (int j = 0; j < 4; j++)
        pix[j] = (jbase + j < cnt) ? g_idx_c[off + jbase + j] : -1;
    #pragma unroll
    for (int i = 0; i < 8; i++) {
        int c = r0 + (ty << 3) + i;
        float cr = corr[c];
        long rowbase = ((long)(b*CC + c)) << 16;
        #pragma unroll
        for (int j = 0; j < 4; j++)
            if (pix[j] >= 0) out[rowbase + pix[j]] = accf[i][j] + cr;
    }
}

// ---------------- launcher ----------------
extern "C" void kernel_launch(void* const* d_in, const int* in_sizes, int n_in,
                              void* d_out, int out_size) {
    const float*        cf = (const float*)d_in[0];
    const float*        sf = (const float*)d_in[1];
    const unsigned int* cm = (const unsigned int*)d_in[2];
    const unsigned int* sm = (const unsigned int*)d_in[3];
    float* out = (float*)d_out;

    k_detect <<<1, 256>>>(cm, sm);
    k_hist   <<<NCHUNK, 256>>>(cm, sm);
    k_off    <<<1, 64>>>();
    k_scatter<<<NCHUNK, 256>>>();
    k_copy   <<<32768, 256>>>(cf, out);
    k_gather <<<dim3(32768, 2), 256>>>(cf, sf);
    k_sum    <<<dim3(CC, BB, 2), 256>>>();
    k_cov    <<<dim3(3*SPLITK, NBL, 2), 256>>>();
    k_covred <<<dim3(64, 3*NBL, 2), 256>>>();
    k_chol   <<<32, 256>>>();
    k_inv    <<<16, 256>>>();
    k_T      <<<dim3(CC, NBL), 256>>>();
    k_color  <<<dim3(1032, 2, BB), 256>>>(out);
}